// round 12
// baseline (speedup 1.0000x reference)
#include <cuda_runtime.h>
#include <cstdint>

// Problem constants
#define N_PIX 4194304      // 4*4*512*512
#define NQ    1048576      // N_PIX / 4  (float4 groups)
#define NB    101          // bins / categories
#define RSTR  108          // padded icdf row stride: 101 data + 7 pads
#define NBK   256          // u-quantile buckets per row

// smem layout (dynamic): [ icdf: NB*RSTR u32 ][ lut: NB*NBK u8 ]
#define CDF_BYTES  (NB * RSTR * 4)            // 43,632
#define LUT_BYTES  (NB * NBK)                 // 25,856
#define SMEM_TOTAL (CDF_BYTES + LUT_BYTES)    // 69,488

// ---------------------------------------------------------------------------
// JAX *partitionable* threefry bits for 32-bit draws, key = jax.random.key(1):
//   (k1,k2) = (0,1);  ks0=0, ks1=1, ks2 = 0^1^0x1BD11BDA = 0x1BD11BDB
//   per element i (size < 2^32): counts_hi = 0, counts_lo = i
//   (y0,y1) = threefry2x32((0,1), (0,i));  bits = y0 ^ y1
// ---------------------------------------------------------------------------
__device__ __forceinline__ uint32_t threefry_bits(uint32_t i) {
    const uint32_t ks0 = 0u;
    const uint32_t ks1 = 1u;
    const uint32_t ks2 = 0x1BD11BDBu;

    uint32_t x0 = 0u + ks0;
    uint32_t x1 = i  + ks1;

#define TF_ROUND(r) do { x0 += x1; x1 = __funnelshift_l(x1, x1, (r)); x1 ^= x0; } while (0)

    TF_ROUND(13); TF_ROUND(15); TF_ROUND(26); TF_ROUND(6);
    x0 += ks1; x1 += ks2 + 1u;
    TF_ROUND(17); TF_ROUND(29); TF_ROUND(16); TF_ROUND(24);
    x0 += ks2; x1 += ks0 + 2u;
    TF_ROUND(13); TF_ROUND(15); TF_ROUND(26); TF_ROUND(6);
    x0 += ks0; x1 += ks1 + 3u;
    TF_ROUND(17); TF_ROUND(29); TF_ROUND(16); TF_ROUND(24);
    x0 += ks1; x1 += ks2 + 4u;
    TF_ROUND(13); TF_ROUND(15); TF_ROUND(26); TF_ROUND(6);
    x0 += ks2; x1 += ks0 + 5u;

#undef TF_ROUND
    return x0 ^ x1;           // partitionable 32-bit combine
}

// digitize(x, arange(0,0.5,0.005)) = # of float32 edges e(j)=j*0.005f with e<=x
__device__ __forceinline__ int refl_bin(float xv) {
    int r = (int)(xv * 200.0f) + 1;
    r = min(r, 100);
    if (r < 100 && (float)r * 0.005f <= xv) ++r;
    if ((float)(r - 1) * 0.005f > xv) --r;
    return r;   // in [0, 100]
}

// Integer-domain mapping:
//   u = v * 2^-23 exactly, v = bits>>9 in [0, 2^23).
//   (cdf[j] < u)  <=>  v > cdf[j]*2^23  <=>  v >= I[j],  I[j] = floor(cdf[j]*2^23)+1
//   answer j* = searchsorted-left(cdf, u) = #{ j : I[j] <= v } = first j with I[j] > v
// cdf[j]*2^23 is an exact fp32 multiply (power of two), so I[j] is exact.

// Branchless lower_bound over 101 integer entries (build only): first j with I[j] > v.
__device__ __forceinline__ int ilb101(const uint32_t* __restrict__ row, uint32_t v) {
    int lo = 0, len = NB;          // 7 steps: 2^7 = 128 >= 102 states
#pragma unroll
    for (int it = 0; it < 7; ++it) {
        int half = len >> 1;
        int mid  = lo + half;
        bool go  = row[mid] <= v;  // I[mid] <= v  -> answer is right of mid
        lo  = go ? (mid + 1)        : lo;
        len = go ? (len - half - 1) : half;
    }
    return lo;
}

// Branchless lower_bound over the fixed window [lo, lo+7] (hot path).
// 8 states, exactly 3 steps (2^3 = 8). Pads (0xFFFFFFFF) at row[101..107]
// keep all probes in-bounds and never <= v. Max probe index = lo+6 <= 106.
__device__ __forceinline__ int ilb_win7(const uint32_t* __restrict__ row,
                                        int lo, uint32_t v) {
    int len = 7;                   // 7 -> 3 -> 1 -> 0
#pragma unroll
    for (int it = 0; it < 3; ++it) {
        int half = len >> 1;
        int mid  = lo + half;
        bool go  = row[mid] <= v;
        lo  = go ? (mid + 1)        : lo;
        len = go ? (len - half - 1) : half;
    }
    return lo;
}

// searchsorted(cdf_row, u, 'left') in integer domain, clipped to [0, 100].
// Exact while every 1/256-bucket span <= 7 (violation needs 8 consecutive
// softmax probs < ~5e-4 each: P ~ 2e-14 over the whole matrix).
__device__ __forceinline__ int sample_idx(const uint32_t* __restrict__ icdf,
                                          const uint8_t* __restrict__ lut,
                                          int r, uint32_t bits) {
    uint32_t v = bits >> 9;                    // 23-bit uniform
    int k  = (int)(bits >> 24);                // v >> 15, bucket 0..255
    int lo = lut[r * NBK + k];
    int j  = ilb_win7(icdf + r * RSTR, lo, v);
    return min(j, NB - 1);
}

__global__ __launch_bounds__(1024, 2)
void noise_model_kernel(const float4* __restrict__ x4,
                        const float*  __restrict__ nm,
                        float4* __restrict__ out4) {
    extern __shared__ __align__(16) unsigned char smem_raw[];
    uint32_t* icdf = (uint32_t*)smem_raw;                // NB * RSTR
    uint8_t*  lut  = (uint8_t*)(smem_raw + CDF_BYTES);   // NB * NBK

    const int tid = threadIdx.x;

    // Build 1: thread t = cumsum of row t (left-to-right, matches XLA),
    // converted to the exact integer threshold I[j], plus pads.
    if (tid < NB) {
        const float* rowp = nm + tid * NB;
        uint32_t*    crow = icdf + tid * RSTR;
        float s = 0.0f;
#pragma unroll 4
        for (int j = 0; j < NB; ++j) {
            s += rowp[j];
            crow[j] = (uint32_t)(s * 8388608.0f) + 1u;   // floor(c*2^23)+1, exact
        }
#pragma unroll
        for (int j = NB; j < RSTR; ++j) crow[j] = 0xFFFFFFFFu;  // pads: never <= v
    }
    __syncthreads();

    // Build 2: all threads fill the bucket LUT (25,856 entries, ~25/thread).
    // lut[r][k] = first j with I[j] > k*2^15  (lower bound for the whole bucket).
    for (int e = tid; e < NB * NBK; e += 1024) {
        int      r  = e >> 8;                 // e / NBK
        int      k  = e & (NBK - 1);
        uint32_t v0 = (uint32_t)k << 15;      // smallest v in bucket k
        int lo = ilb101(icdf + r * RSTR, v0);
        lut[e] = (uint8_t)min(lo, NB - 1);
    }
    __syncthreads();

    const int stride = blockDim.x * gridDim.x;
#pragma unroll 1
    for (int g = blockIdx.x * blockDim.x + tid; g < NQ; g += stride) {
        const uint32_t base = (uint32_t)g * 4u;

        // 4 independent threefry evaluations (ILP)
        uint32_t b0 = threefry_bits(base + 0u);
        uint32_t b1 = threefry_bits(base + 1u);
        uint32_t b2 = threefry_bits(base + 2u);
        uint32_t b3 = threefry_bits(base + 3u);

        float4 xv = x4[g];

        int i0 = sample_idx(icdf, lut, refl_bin(xv.x), b0);
        int i1 = sample_idx(icdf, lut, refl_bin(xv.y), b1);
        int i2 = sample_idx(icdf, lut, refl_bin(xv.z), b2);
        int i3 = sample_idx(icdf, lut, refl_bin(xv.w), b3);

        // noisy_ranges[idx] = -0.0101f + 0.0002f * idx (float32, matches jnp)
        float4 o;
        o.x = -0.0101f + 0.0002f * (float)i0;
        o.y = -0.0101f + 0.0002f * (float)i1;
        o.z = -0.0101f + 0.0002f * (float)i2;
        o.w = -0.0101f + 0.0002f * (float)i3;
        out4[g] = o;
    }
}

extern "C" void kernel_launch(void* const* d_in, const int* in_sizes, int n_in,
                              void* d_out, int out_size) {
    // Disambiguate inputs by size: x has 4194304 elems, noise_matrix has 10201.
    const float* a = (const float*)d_in[0];
    const float* b = (const float*)d_in[1];
    const float* x  = a;
    const float* nm = b;
    if (n_in >= 2 && in_sizes[0] < in_sizes[1]) { x = b; nm = a; }
    float* out = (float*)d_out;
    (void)out_size;

    cudaFuncSetAttribute(noise_model_kernel,
                         cudaFuncAttributeMaxDynamicSharedMemorySize,
                         SMEM_TOTAL);

    noise_model_kernel<<<296, 1024, SMEM_TOTAL>>>((const float4*)x, nm, (float4*)out);
}

// round 13
// speedup vs baseline: 1.3330x; 1.3330x over previous
#include <cuda_runtime.h>
#include <cstdint>

// Problem constants
#define N_PIX 4194304      // 4*4*512*512
#define NQ    1048576      // N_PIX / 4  (float4 groups)
#define NB    101          // bins / categories
#define RSTR  108          // padded icdf row stride: 101 data + 7 pads
#define NBK   256          // u-quantile buckets per row

// smem layout (dynamic): [ icdf: NB*RSTR u32 ][ lut: NB*NBK u8 ]
#define CDF_WORDS  (NB * RSTR)                // 10,908 u32
#define CDF_BYTES  (CDF_WORDS * 4)            // 43,632
#define LUT_WORDS  (NB * NBK / 4)             //  6,464 u32
#define LUT_BYTES  (NB * NBK)                 // 25,856
#define SMEM_TOTAL (CDF_BYTES + LUT_BYTES)    // 69,488

// Precomputed tables in global scratch (static device arrays: allowed).
__device__ uint32_t g_icdf[CDF_WORDS];
__device__ uint32_t g_lut32[LUT_WORDS];

// ---------------------------------------------------------------------------
// JAX *partitionable* threefry bits for 32-bit draws, key = jax.random.key(1):
//   (k1,k2) = (0,1);  ks0=0, ks1=1, ks2 = 0^1^0x1BD11BDA = 0x1BD11BDB
//   per element i (size < 2^32): counts_hi = 0, counts_lo = i
//   (y0,y1) = threefry2x32((0,1), (0,i));  bits = y0 ^ y1
// ---------------------------------------------------------------------------
__device__ __forceinline__ uint32_t threefry_bits(uint32_t i) {
    const uint32_t ks0 = 0u;
    const uint32_t ks1 = 1u;
    const uint32_t ks2 = 0x1BD11BDBu;

    uint32_t x0 = 0u + ks0;
    uint32_t x1 = i  + ks1;

#define TF_ROUND(r) do { x0 += x1; x1 = __funnelshift_l(x1, x1, (r)); x1 ^= x0; } while (0)

    TF_ROUND(13); TF_ROUND(15); TF_ROUND(26); TF_ROUND(6);
    x0 += ks1; x1 += ks2 + 1u;
    TF_ROUND(17); TF_ROUND(29); TF_ROUND(16); TF_ROUND(24);
    x0 += ks2; x1 += ks0 + 2u;
    TF_ROUND(13); TF_ROUND(15); TF_ROUND(26); TF_ROUND(6);
    x0 += ks0; x1 += ks1 + 3u;
    TF_ROUND(17); TF_ROUND(29); TF_ROUND(16); TF_ROUND(24);
    x0 += ks1; x1 += ks2 + 4u;
    TF_ROUND(13); TF_ROUND(15); TF_ROUND(26); TF_ROUND(6);
    x0 += ks2; x1 += ks0 + 5u;

#undef TF_ROUND
    return x0 ^ x1;           // partitionable 32-bit combine
}

// digitize(x, arange(0,0.5,0.005)) = # of float32 edges e(j)=j*0.005f with e<=x
__device__ __forceinline__ int refl_bin(float xv) {
    int r = (int)(xv * 200.0f) + 1;
    r = min(r, 100);
    if (r < 100 && (float)r * 0.005f <= xv) ++r;
    if ((float)(r - 1) * 0.005f > xv) --r;
    return r;   // in [0, 100]
}

// Integer-domain mapping:
//   u = v * 2^-23 exactly, v = bits>>9 in [0, 2^23).
//   (cdf[j] < u)  <=>  v >= I[j],  I[j] = floor(cdf[j]*2^23)+1   (exact)
//   searchsorted-left(cdf, u) = first j with I[j] > v.

// Branchless lower_bound over 101 integer entries: first j with I[j] > v.
__device__ __forceinline__ int ilb101(const uint32_t* __restrict__ row, uint32_t v) {
    int lo = 0, len = NB;          // 7 steps: 2^7 = 128 >= 102 states
#pragma unroll
    for (int it = 0; it < 7; ++it) {
        int half = len >> 1;
        int mid  = lo + half;
        bool go  = row[mid] <= v;
        lo  = go ? (mid + 1)        : lo;
        len = go ? (len - half - 1) : half;
    }
    return lo;
}

// Branchless lower_bound over the fixed window [lo, lo+7]: 8 states, 3 steps.
// Pads (0xFFFFFFFF) at row[101..107] keep probes in-bounds and never <= v.
__device__ __forceinline__ int ilb_win7(const uint32_t* __restrict__ row,
                                        int lo, uint32_t v) {
    int len = 7;                   // 7 -> 3 -> 1 -> 0
#pragma unroll
    for (int it = 0; it < 3; ++it) {
        int half = len >> 1;
        int mid  = lo + half;
        bool go  = row[mid] <= v;
        lo  = go ? (mid + 1)        : lo;
        len = go ? (len - half - 1) : half;
    }
    return lo;
}

// searchsorted(cdf_row, u, 'left') in integer domain, clipped to [0, 100].
// Exact while every 1/256-bucket span <= 7 (P(violation) ~ 2e-14 total).
__device__ __forceinline__ int sample_idx(const uint32_t* __restrict__ icdf,
                                          const uint8_t* __restrict__ lut,
                                          int r, uint32_t bits) {
    uint32_t v = bits >> 9;                    // 23-bit uniform
    int k  = (int)(bits >> 24);                // bucket 0..255
    int lo = lut[r * NBK + k];
    int j  = ilb_win7(icdf + r * RSTR, lo, v);
    return min(j, NB - 1);
}

// ---------------------------------------------------------------------------
// Kernel A: build the integer CDF + bucket LUT ONCE into global scratch.
// Grid: 101 blocks (one per row) x 256 threads (one per LUT entry).
// ---------------------------------------------------------------------------
__global__ void build_kernel(const float* __restrict__ nm) {
    __shared__ uint32_t srow[RSTR];
    const int r = blockIdx.x;
    const int t = threadIdx.x;

    if (t == 0) {
        const float* rowp = nm + r * NB;
        float s = 0.0f;
#pragma unroll 4
        for (int j = 0; j < NB; ++j) {
            s += rowp[j];
            srow[j] = (uint32_t)(s * 8388608.0f) + 1u;   // floor(c*2^23)+1, exact
        }
#pragma unroll
        for (int j = NB; j < RSTR; ++j) srow[j] = 0xFFFFFFFFu;
    }
    __syncthreads();

    // One LUT entry per thread: first j with I[j] > t*2^15.
    uint32_t v0 = (uint32_t)t << 15;
    int lo = ilb101(srow, v0);
    ((uint8_t*)g_lut32)[r * NBK + t] = (uint8_t)min(lo, NB - 1);

    // Copy the row out.
    if (t < RSTR) g_icdf[r * RSTR + t] = srow[t];
}

// ---------------------------------------------------------------------------
// Kernel B: copy tables gmem->smem (cheap, coalesced), then the hot loop.
// ---------------------------------------------------------------------------
__global__ __launch_bounds__(1024, 2)
void noise_model_kernel(const float4* __restrict__ x4,
                        float4* __restrict__ out4) {
    extern __shared__ __align__(16) unsigned char smem_raw[];
    uint32_t* icdf  = (uint32_t*)smem_raw;                // NB * RSTR
    uint32_t* lut32 = (uint32_t*)(smem_raw + CDF_BYTES);  // NB * NBK / 4
    const uint8_t* lut = (const uint8_t*)lut32;

    const int tid = threadIdx.x;

    // Table copy: ~11 + ~7 coalesced words per thread.
#pragma unroll 1
    for (int i = tid; i < CDF_WORDS; i += 1024) icdf[i]  = g_icdf[i];
#pragma unroll 1
    for (int i = tid; i < LUT_WORDS; i += 1024) lut32[i] = g_lut32[i];
    __syncthreads();

    const int stride = blockDim.x * gridDim.x;
#pragma unroll 1
    for (int g = blockIdx.x * blockDim.x + tid; g < NQ; g += stride) {
        const uint32_t base = (uint32_t)g * 4u;

        // 4 independent threefry evaluations (ILP)
        uint32_t b0 = threefry_bits(base + 0u);
        uint32_t b1 = threefry_bits(base + 1u);
        uint32_t b2 = threefry_bits(base + 2u);
        uint32_t b3 = threefry_bits(base + 3u);

        float4 xv = x4[g];

        int i0 = sample_idx(icdf, lut, refl_bin(xv.x), b0);
        int i1 = sample_idx(icdf, lut, refl_bin(xv.y), b1);
        int i2 = sample_idx(icdf, lut, refl_bin(xv.z), b2);
        int i3 = sample_idx(icdf, lut, refl_bin(xv.w), b3);

        // noisy_ranges[idx] = -0.0101f + 0.0002f * idx (float32, matches jnp)
        float4 o;
        o.x = -0.0101f + 0.0002f * (float)i0;
        o.y = -0.0101f + 0.0002f * (float)i1;
        o.z = -0.0101f + 0.0002f * (float)i2;
        o.w = -0.0101f + 0.0002f * (float)i3;
        out4[g] = o;
    }
}

extern "C" void kernel_launch(void* const* d_in, const int* in_sizes, int n_in,
                              void* d_out, int out_size) {
    // Disambiguate inputs by size: x has 4194304 elems, noise_matrix has 10201.
    const float* a = (const float*)d_in[0];
    const float* b = (const float*)d_in[1];
    const float* x  = a;
    const float* nm = b;
    if (n_in >= 2 && in_sizes[0] < in_sizes[1]) { x = b; nm = a; }
    float* out = (float*)d_out;
    (void)out_size;

    cudaFuncSetAttribute(noise_model_kernel,
                         cudaFuncAttributeMaxDynamicSharedMemorySize,
                         SMEM_TOTAL);

    // A: build tables once (101 blocks x 256 threads).
    build_kernel<<<NB, NBK>>>(nm);
    // B: main pass; same stream so ordering is guaranteed under graph capture.
    noise_model_kernel<<<296, 1024, SMEM_TOTAL>>>((const float4*)x, (float4*)out);
}